// round 9
// baseline (speedup 1.0000x reference)
#include <cuda_runtime.h>

#define TT 8192
#define H 512
#define NCTA 64
#define NTHREADS 256
#define HPC 8          // h outputs per CTA
#define NCTR 8         // barrier counters (CTA b -> counter b&7)
#define PADC 32        // 32 uints = one 128B line per counter
#define FULLMASK 0xffffffffu

// Static scratch (no allocations allowed)
__device__ float g_h1[TT * H];       // layer-0 hidden states history (16 MB)
__device__ float g_hbuf[2][H];       // double-buffered h exchange (hot 4KB)
__device__ float g_hfinal[H];        // final h2
__device__ unsigned g_bar8[NCTR * PADC];   // 8 padded barrier counters

// ---------- helpers ----------
__device__ __forceinline__ unsigned long long pack2(float lo, float hi) {
    unsigned long long r;
    asm("mov.b64 %0,{%1,%2};" : "=l"(r) : "f"(lo), "f"(hi));
    return r;
}
__device__ __forceinline__ void unpack2(unsigned long long v, float& lo, float& hi) {
    asm("mov.b64 {%0,%1},%2;" : "=f"(lo), "=f"(hi) : "l"(v));
}
// packed fp32x2 FMA: 2 MACs per instruction (PTX-only on Blackwell)
__device__ __forceinline__ void fma2(unsigned long long& acc, unsigned long long a, unsigned long long b) {
    asm("fma.rn.f32x2 %0,%1,%2,%0;" : "+l"(acc) : "l"(a), "l"(b));
}
__device__ __forceinline__ float4 ldcg4(const float4* p) {
    float4 v;
    asm volatile("ld.global.cg.v4.f32 {%0,%1,%2,%3},[%4];"
                 : "=f"(v.x), "=f"(v.y), "=f"(v.z), "=f"(v.w) : "l"(p));
    return v;
}
__device__ __forceinline__ unsigned ldrlx(const unsigned* p) {
    unsigned v;
    asm volatile("ld.relaxed.gpu.u32 %0,[%1];" : "=r"(v) : "l"(p));
    return v;
}
__device__ __forceinline__ void redrel(unsigned* p) {
    asm volatile("red.release.gpu.global.add.u32 [%0],1;" :: "l"(p));
}
__device__ __forceinline__ void fence_acq() {
    asm volatile("fence.acq_rel.gpu;" ::: "memory");
}
__device__ __forceinline__ float tanhfast(float x) {
    float y; asm("tanh.approx.f32 %0,%1;" : "=f"(y) : "f"(x)); return y;
}

// ---------- init: reset barrier counters + h double buffer ----------
__global__ void init_kernel() {
    int t = threadIdx.x;
    if (t < NCTR * PADC) g_bar8[t] = 0u;
    for (int i = t; i < 2 * H; i += blockDim.x) ((float*)g_hbuf)[i] = 0.0f;
}

// ---------- persistent LSTM layer (R8 structure + release arrivals + pipelined poll) ----------
// 64 CTAs x 256 threads. CTA b owns h indices [b*8, b*8+8) -> 32 gate rows.
// Warp w covers h columns [w*64, w*64+64); lane l = local gate row:
// lane 0..7 = i rows, 8..15 = f, 16..23 = g, 24..31 = o.
template <int LAYER>
__global__ void __launch_bounds__(NTHREADS, 1) lstm_kernel(
    const float* __restrict__ x,      // layer0: input_seq [T] (NC=1). layer1: unused
    const float* __restrict__ w_ih,   // layer0: [2048,1]; layer1: [2048,512]
    const float* __restrict__ w_hh,   // [2048,512]
    const float* __restrict__ b_ih,   // [2048]
    const float* __restrict__ b_hh)   // [2048]
{
    const int tid = threadIdx.x;
    const int w = tid >> 5;           // warp id 0..7 (column chunk)
    const int l = tid & 31;           // lane = local gate row 0..31
    const int b = blockIdx.x;
    const int sec = l >> 3;           // 0:i 1:f 2:g 3:o
    const int j8 = l & 7;
    const int grow = sec * H + b * HPC + j8;  // global gate row

    __shared__ float red[8][33];
    __shared__ float sx[(LAYER == 0) ? TT : 1];

    if (LAYER == 0) {
        for (int i = tid; i < TT; i += NTHREADS) sx[i] = x[i];
    }

    // Preload recurrent weights into registers (64 floats/thread per matrix)
    unsigned long long whh[32];
    {
        const float* wr = w_hh + (size_t)grow * H + w * 64;
#pragma unroll
        for (int k = 0; k < 16; k++) {
            float4 v = *(const float4*)(wr + 4 * k);
            whh[2 * k] = pack2(v.x, v.y);
            whh[2 * k + 1] = pack2(v.z, v.w);
        }
    }
    unsigned long long wihr[32];
    if (LAYER == 1) {
        const float* wr = w_ih + (size_t)grow * H + w * 64;
#pragma unroll
        for (int k = 0; k < 16; k++) {
            float4 v = *(const float4*)(wr + 4 * k);
            wihr[2 * k] = pack2(v.x, v.y);
            wihr[2 * k + 1] = pack2(v.z, v.w);
        }
    }
    const float bias = b_ih[grow] + b_hh[grow];
    const float wx = (LAYER == 0) ? w_ih[grow] : 0.0f;  // NC = 1
    float c = 0.0f;                                      // cell state (lanes 0..7 of warp 0)
    __syncthreads();

    for (int t = 0; t < TT; t++) {
        const int p = t & 1;
        // hoist x_t load (hide LDS latency behind the matvec)
        const float xt = (LAYER == 0) ? sx[t] : 0.0f;

        // --- mat-vec: acc = W_hh[row, wcols] . h_prev[wcols] (+ W_ih . h1[t] for layer 1)
        unsigned long long a0 = 0ull, a1 = 0ull;  // bits 0 == (0.f, 0.f)
        const float4* hb = ((const float4*)g_hbuf[p]) + w * 16;
#pragma unroll
        for (int k = 0; k < 16; k++) {
            float4 hv = ldcg4(hb + k);
            fma2(a0, whh[2 * k], pack2(hv.x, hv.y));
            fma2(a1, whh[2 * k + 1], pack2(hv.z, hv.w));
        }
        if (LAYER == 1) {
            const float4* h1p = ((const float4*)g_h1) + (size_t)t * (H / 4) + w * 16;
#pragma unroll
            for (int k = 0; k < 16; k++) {
                float4 hv = __ldg(h1p + k);
                fma2(a0, wihr[2 * k], pack2(hv.x, hv.y));
                fma2(a1, wihr[2 * k + 1], pack2(hv.z, hv.w));
            }
        }
        float lo0, hi0, lo1, hi1;
        unpack2(a0, lo0, hi0);
        unpack2(a1, lo1, hi1);
        red[w][l] = (lo0 + hi0) + (lo1 + hi1);
        __syncthreads();

        if (w == 0) {
            float s = red[0][l];
#pragma unroll
            for (int q = 1; q < 8; q++) s += red[q][l];
            float gv = s + bias;
            if (LAYER == 0) gv += xt * wx;
            // --- single-MUFU activation per lane: sec==2 -> tanh, else sigmoid
            const bool isg = (sec == 2);
            float arg = isg ? gv : (0.5f * gv);
            float th = tanhfast(arg);
            float act = isg ? th : fmaf(0.5f, th, 0.5f);
            // gather f/g/o activations onto the i-lane for the same j
            float ff = __shfl_sync(FULLMASK, act, l + 8);
            float gg = __shfl_sync(FULLMASK, act, l + 16);
            float oo = __shfl_sync(FULLMASK, act, l + 24);
            if (l < 8) {
                float ii = act;
                c = ff * c + ii * gg;
                float hn = oo * tanhfast(c);
                int hj = b * HPC + l;
                g_hbuf[p ^ 1][hj] = hn;
                if (LAYER == 0) g_h1[(size_t)t * H + hj] = hn;
                else if (t == TT - 1) g_hfinal[hj] = hn;
                // per-lane release arrival: orders THIS lane's stores, no fence needed
                redrel(&g_bar8[(b & 7) * PADC]);
            }
        }

        if (t != TT - 1) {
            // --- barrier detect (warp 1, overlapped with warp 0's gate phase):
            // 4 software-pipelined relaxed probes -> counter sampled ~every RTT/4
            if (w == 1) {
                const unsigned tgt = 64u * (unsigned)(t + 1);   // 8 CTAs x 8 lanes per counter
                const unsigned* cp = &g_bar8[(l & 7) * PADC];
                unsigned p0 = ldrlx(cp), p1 = ldrlx(cp), p2 = ldrlx(cp), p3 = ldrlx(cp);
                for (;;) {
                    if (p0 >= tgt) break; p0 = ldrlx(cp);
                    if (p1 >= tgt) break; p1 = ldrlx(cp);
                    if (p2 >= tgt) break; p2 = ldrlx(cp);
                    if (p3 >= tgt) break; p3 = ldrlx(cp);
                }
                fence_acq();   // upgrade relaxed observation to acquire
            }
            __syncthreads();   // propagate visibility block-wide, release all warps
        }
    }
}

// ---------- MLP head on final h2 ----------
__global__ void head_kernel(const float* __restrict__ w1, const float* __restrict__ b1,
                            const float* __restrict__ w2, const float* __restrict__ b2,
                            float* __restrict__ out)
{
    __shared__ float y1[32];
    const int tid = threadIdx.x, w = tid >> 5, l = tid & 31;
    for (int r = w; r < 20; r += 8) {
        float acc = 0.0f;
        for (int k = l; k < H; k += 32) acc += g_hfinal[k] * w1[r * H + k];
#pragma unroll
        for (int off = 16; off; off >>= 1) acc += __shfl_xor_sync(FULLMASK, acc, off);
        if (l == 0) y1[r] = acc + b1[r];
    }
    __syncthreads();
    if (tid == 0) {
        float o = b2[0];
#pragma unroll
        for (int r = 0; r < 20; r++) o += y1[r] * w2[r];
        out[0] = o;
    }
}

extern "C" void kernel_launch(void* const* d_in, const int* in_sizes, int n_in,
                              void* d_out, int out_size)
{
    const float* x    = (const float*)d_in[0];
    const float* wih0 = (const float*)d_in[1];
    const float* whh0 = (const float*)d_in[2];
    const float* bih0 = (const float*)d_in[3];
    const float* bhh0 = (const float*)d_in[4];
    const float* wih1 = (const float*)d_in[5];
    const float* whh1 = (const float*)d_in[6];
    const float* bih1 = (const float*)d_in[7];
    const float* bhh1 = (const float*)d_in[8];
    const float* w1   = (const float*)d_in[9];
    const float* b1   = (const float*)d_in[10];
    const float* w2   = (const float*)d_in[11];
    const float* b2   = (const float*)d_in[12];
    float* out = (float*)d_out;

    init_kernel<<<1, 256>>>();
    lstm_kernel<0><<<NCTA, NTHREADS>>>(x, wih0, whh0, bih0, bhh0);
    init_kernel<<<1, 256>>>();
    lstm_kernel<1><<<NCTA, NTHREADS>>>(nullptr, wih1, whh1, bih1, bhh1);
    head_kernel<<<1, 256>>>(w1, b1, w2, b2, out);
}

// round 10
// speedup vs baseline: 1.5097x; 1.5097x over previous
#include <cuda_runtime.h>

#define TT 8192
#define H 512
#define NCTA_L 64      // CTAs per layer
#define NCTA 128       // total CTAs
#define NTHREADS 256
#define HPC 8          // h outputs per CTA
#define NCTR 8         // barrier counters (CTA b -> counter b&7; 16 CTAs each)
#define PADC 32        // 32 uints = one 128B line per counter
#define FULLMASK 0xffffffffu

// Static scratch (no allocations allowed)
__device__ float g_h1buf[2][H];      // h1 exchange ring (hot 4KB)
__device__ float g_h2buf[2][H];      // h2 exchange ring
__device__ float g_hfinal[H];        // final h2
__device__ unsigned g_bar8[NCTR * PADC];   // 8 padded barrier counters

// ---------- helpers ----------
__device__ __forceinline__ unsigned long long pack2(float lo, float hi) {
    unsigned long long r;
    asm("mov.b64 %0,{%1,%2};" : "=l"(r) : "f"(lo), "f"(hi));
    return r;
}
__device__ __forceinline__ void unpack2(unsigned long long v, float& lo, float& hi) {
    asm("mov.b64 {%0,%1},%2;" : "=f"(lo), "=f"(hi) : "l"(v));
}
// packed fp32x2 FMA: 2 MACs per instruction (PTX-only on Blackwell)
__device__ __forceinline__ void fma2(unsigned long long& acc, unsigned long long a, unsigned long long b) {
    asm("fma.rn.f32x2 %0,%1,%2,%0;" : "+l"(acc) : "l"(a), "l"(b));
}
__device__ __forceinline__ float4 ldcg4(const float4* p) {
    float4 v;
    asm volatile("ld.global.cg.v4.f32 {%0,%1,%2,%3},[%4];"
                 : "=f"(v.x), "=f"(v.y), "=f"(v.z), "=f"(v.w) : "l"(p));
    return v;
}
__device__ __forceinline__ unsigned ldacq(const unsigned* p) {
    unsigned v;
    asm volatile("ld.acquire.gpu.u32 %0,[%1];" : "=r"(v) : "l"(p));
    return v;
}
__device__ __forceinline__ float tanhfast(float x) {
    float y; asm("tanh.approx.f32 %0,%1;" : "=f"(y) : "f"(x)); return y;
}
__device__ __forceinline__ float sigfast(float x) { return 0.5f * tanhfast(0.5f * x) + 0.5f; }

// ---------- init: reset barrier counters ----------
__global__ void init_kernel() {
    int t = threadIdx.x;
    if (t < NCTR * PADC) g_bar8[t] = 0u;
}

// ---------- fused superstep-pipelined 2-layer LSTM (R8 substrate) ----------
// 128 CTAs x 256 threads (single wave). CTAs [0,64): layer 0; [64,128): layer 1.
// Superstep s: L0 computes h1(s) (s<TT); L1 computes h2(s-1) (s>=1).
// ONE barrier per superstep -> 8193 barriers instead of 16384.
// Within a CTA (R8 layout): CTA owns 8 outputs -> 32 gate rows. Warp w covers
// columns [w*64,(w+1)*64); lane l = local gate row (0..7=i, 8..15=f, 16..23=g, 24..31=o).
__global__ void __launch_bounds__(NTHREADS, 1) lstm2_kernel(
    const float* __restrict__ x,
    const float* __restrict__ wih0, const float* __restrict__ whh0,
    const float* __restrict__ bih0, const float* __restrict__ bhh0,
    const float* __restrict__ wih1, const float* __restrict__ whh1,
    const float* __restrict__ bih1, const float* __restrict__ bhh1)
{
    const int tid = threadIdx.x;
    const int w = tid >> 5;
    const int l = tid & 31;
    const int bg_ = blockIdx.x;
    const bool is0 = bg_ < NCTA_L;
    const int b = is0 ? bg_ : (bg_ - NCTA_L);
    const int sec = l >> 3;
    const int j8 = l & 7;
    const int grow = sec * H + b * HPC + j8;   // gate row within this CTA's layer

    __shared__ float red[8][33];
    __shared__ float sx[TT];                   // filled by L0 CTAs only (32KB, 1 CTA/SM)
    if (is0) for (int i = tid; i < TT; i += NTHREADS) sx[i] = x[i];

    // recurrent weights -> registers (64 floats/thread)
    unsigned long long whh[32];
    {
        const float* wr = (is0 ? whh0 : whh1) + (size_t)grow * H + w * 64;
#pragma unroll
        for (int k = 0; k < 16; k++) {
            float4 v = *(const float4*)(wr + 4 * k);
            whh[2 * k] = pack2(v.x, v.y);
            whh[2 * k + 1] = pack2(v.z, v.w);
        }
    }
    // layer-1 input weights -> registers (64 more floats; L1 CTAs only)
    unsigned long long wihr[32];
    if (!is0) {
        const float* wr = wih1 + (size_t)grow * H + w * 64;
#pragma unroll
        for (int k = 0; k < 16; k++) {
            float4 v = *(const float4*)(wr + 4 * k);
            wihr[2 * k] = pack2(v.x, v.y);
            wihr[2 * k + 1] = pack2(v.z, v.w);
        }
    }
    const float bias = (is0 ? (bih0[grow] + bhh0[grow]) : (bih1[grow] + bhh1[grow]));
    const float wx = is0 ? wih0[grow] : 0.0f;   // NC = 1
    float c = 0.0f;                              // cell state (lanes 0..7 of warp 0)
    __syncthreads();

    for (int s = 0; s <= TT; s++) {
        // ---- barrier detect: everyone finished superstep s-1 (R8 poll, target 16*s)
        if (s > 0) {
            if (tid < 32) {
                const unsigned tgt = 16u * (unsigned)s;
                const unsigned* cp = &g_bar8[(l & 7) * PADC];
                for (;;) {
                    unsigned v = ldacq(cp);
                    if (__all_sync(FULLMASK, v >= tgt)) break;
                }
            }
            __syncthreads();
        }

        const bool active = is0 ? (s < TT) : (s >= 1);

        // ---- mat-vec
        unsigned long long a0 = 0ull, a1 = 0ull;
        if (active) {
            if (is0) {
                if (s > 0) {   // W_hh0 . h1(s-1)
                    const float4* hb = ((const float4*)g_h1buf[(s - 1) & 1]) + w * 16;
#pragma unroll
                    for (int k = 0; k < 16; k++) {
                        float4 hv = ldcg4(hb + k);
                        fma2(a0, whh[2 * k], pack2(hv.x, hv.y));
                        fma2(a1, whh[2 * k + 1], pack2(hv.z, hv.w));
                    }
                }
            } else {
                {              // W_ih1 . h1(s-1)
                    const float4* hb = ((const float4*)g_h1buf[(s - 1) & 1]) + w * 16;
#pragma unroll
                    for (int k = 0; k < 16; k++) {
                        float4 hv = ldcg4(hb + k);
                        fma2(a0, wihr[2 * k], pack2(hv.x, hv.y));
                        fma2(a1, wihr[2 * k + 1], pack2(hv.z, hv.w));
                    }
                }
                if (s > 1) {   // W_hh1 . h2(s-2)
                    const float4* hb = ((const float4*)g_h2buf[(s - 2) & 1]) + w * 16;
#pragma unroll
                    for (int k = 0; k < 16; k++) {
                        float4 hv = ldcg4(hb + k);
                        fma2(a0, whh[2 * k], pack2(hv.x, hv.y));
                        fma2(a1, whh[2 * k + 1], pack2(hv.z, hv.w));
                    }
                }
            }
        }
        float lo0, hi0, lo1, hi1;
        unpack2(a0, lo0, hi0);
        unpack2(a1, lo1, hi1);
        red[w][l] = (lo0 + hi0) + (lo1 + hi1);
        __syncthreads();

        // ---- gates + publish + arrive (warp 0; R8-proven sequence)
        if (w == 0) {
            if (active) {
                float sum = red[0][l];
#pragma unroll
                for (int q = 1; q < 8; q++) sum += red[q][l];
                float gv = sum + bias;
                if (is0) gv += sx[s] * wx;
                float fv = __shfl_sync(FULLMASK, gv, l + 8);
                float gg = __shfl_sync(FULLMASK, gv, l + 16);
                float ov = __shfl_sync(FULLMASK, gv, l + 24);
                if (l < 8) {
                    float iv = sigfast(gv);
                    float ff = sigfast(fv);
                    float gt = tanhfast(gg);
                    float oo = sigfast(ov);
                    c = ff * c + iv * gt;
                    float hn = oo * tanhfast(c);
                    int hj = b * HPC + l;
                    if (is0) {
                        g_h1buf[s & 1][hj] = hn;                 // publish h1(s)
                    } else {
                        g_h2buf[(s - 1) & 1][hj] = hn;           // publish h2(s-1)
                        if (s == TT) g_hfinal[hj] = hn;
                    }
                }
            }
            __syncwarp();
            if (l == 0 && s < TT) {
                __threadfence();                                  // order stores
                atomicAdd(&g_bar8[(bg_ & 7) * PADC], 1u);        // arrive
            }
        }
    }
}

// ---------- MLP head on final h2 ----------
__global__ void head_kernel(const float* __restrict__ w1, const float* __restrict__ b1,
                            const float* __restrict__ w2, const float* __restrict__ b2,
                            float* __restrict__ out)
{
    __shared__ float y1[32];
    const int tid = threadIdx.x, w = tid >> 5, l = tid & 31;
    for (int r = w; r < 20; r += 8) {
        float acc = 0.0f;
        for (int k = l; k < H; k += 32) acc += g_hfinal[k] * w1[r * H + k];
#pragma unroll
        for (int off = 16; off; off >>= 1) acc += __shfl_xor_sync(FULLMASK, acc, off);
        if (l == 0) y1[r] = acc + b1[r];
    }
    __syncthreads();
    if (tid == 0) {
        float o = b2[0];
#pragma unroll
        for (int r = 0; r < 20; r++) o += y1[r] * w2[r];
        out[0] = o;
    }
}

extern "C" void kernel_launch(void* const* d_in, const int* in_sizes, int n_in,
                              void* d_out, int out_size)
{
    const float* x    = (const float*)d_in[0];
    const float* wih0 = (const float*)d_in[1];
    const float* whh0 = (const float*)d_in[2];
    const float* bih0 = (const float*)d_in[3];
    const float* bhh0 = (const float*)d_in[4];
    const float* wih1 = (const float*)d_in[5];
    const float* whh1 = (const float*)d_in[6];
    const float* bih1 = (const float*)d_in[7];
    const float* bhh1 = (const float*)d_in[8];
    const float* w1   = (const float*)d_in[9];
    const float* b1   = (const float*)d_in[10];
    const float* w2   = (const float*)d_in[11];
    const float* b2   = (const float*)d_in[12];
    float* out = (float*)d_out;

    init_kernel<<<1, 256>>>();
    lstm2_kernel<<<NCTA, NTHREADS>>>(x, wih0, whh0, bih0, bhh0,
                                     wih1, whh1, bih1, bhh1);
    head_kernel<<<1, 256>>>(w1, b1, w2, b2, out);
}